// round 6
// baseline (speedup 1.0000x reference)
#include <cuda_runtime.h>
#include <cuda_bf16.h>
#include <cstdint>
#include <cstddef>

#define D_MODEL 2048
#define N_EXP 8
#define T_TOK 8192
#define BM 128
#define BN 128
#define BK 64
#define KIT (D_MODEL / BK)
#define NTHREADS 256
#define LOSS_SCALE 3e-06f

// ---------------- device global scratch (no allocations allowed) ------------
__device__ int   g_cnt[N_EXP];
__device__ int   g_cur[N_EXP];
__device__ int   g_off[N_EXP];
__device__ float g_tsum[N_EXP];
__device__ int   g_idx[T_TOK];
__device__ float g_topp[T_TOK];
__device__ int   g_list[T_TOK];

// bf16 hi/lo splits, precomputed once per launch
__device__ __nv_bfloat16 g_Whi[(size_t)N_EXP * D_MODEL * D_MODEL];
__device__ __nv_bfloat16 g_Wlo[(size_t)N_EXP * D_MODEL * D_MODEL];
__device__ __nv_bfloat16 g_Xhi[(size_t)T_TOK * D_MODEL];
__device__ __nv_bfloat16 g_Xlo[(size_t)T_TOK * D_MODEL];

// ---------------- helpers ----------------------------------------------------
__device__ __forceinline__ uint32_t smem_u32(const void* p) {
    uint32_t a;
    asm("{ .reg .u64 t; cvta.to.shared.u64 t, %1; cvt.u32.u64 %0, t; }"
        : "=r"(a) : "l"(p));
    return a;
}

#define CP_ASYNC16(dst, src) \
    asm volatile("cp.async.cg.shared.global [%0], [%1], 16;" \
        :: "r"(dst), "l"(src))
#define CP_COMMIT() asm volatile("cp.async.commit_group;")
#define CP_WAIT1()  asm volatile("cp.async.wait_group 1;")
#define CP_WAIT0()  asm volatile("cp.async.wait_group 0;")

__device__ __forceinline__ void ldsm4(uint32_t& r0, uint32_t& r1, uint32_t& r2,
                                      uint32_t& r3, uint32_t addr) {
    asm volatile("ldmatrix.sync.aligned.m8n8.x4.shared.b16 {%0,%1,%2,%3}, [%4];"
                 : "=r"(r0), "=r"(r1), "=r"(r2), "=r"(r3) : "r"(addr));
}

__device__ __forceinline__ void mma16816(float* c, const uint32_t* a,
                                         uint32_t b0, uint32_t b1) {
    asm volatile(
        "mma.sync.aligned.m16n8k16.row.col.f32.bf16.bf16.f32 "
        "{%0,%1,%2,%3}, {%4,%5,%6,%7}, {%8,%9}, {%0,%1,%2,%3};"
        : "+f"(c[0]), "+f"(c[1]), "+f"(c[2]), "+f"(c[3])
        : "r"(a[0]), "r"(a[1]), "r"(a[2]), "r"(a[3]), "r"(b0), "r"(b1));
}

union U32B2 { uint32_t u; __nv_bfloat162 b; };

__device__ __forceinline__ void split2(float x, float y, uint32_t& hi, uint32_t& lo) {
    __nv_bfloat16 hx = __float2bfloat16_rn(x);
    __nv_bfloat16 hy = __float2bfloat16_rn(y);
    __nv_bfloat16 lx = __float2bfloat16_rn(x - __bfloat162float(hx));
    __nv_bfloat16 ly = __float2bfloat16_rn(y - __bfloat162float(hy));
    U32B2 t;
    t.b.x = hx; t.b.y = hy; hi = t.u;
    t.b.x = lx; t.b.y = ly; lo = t.u;
}

// ---------------- small kernels ----------------------------------------------
__global__ void init_kernel() {
    int i = threadIdx.x;
    if (i < N_EXP) { g_cnt[i] = 0; g_cur[i] = 0; g_tsum[i] = 0.f; }
}

// fp32 -> bf16 hi/lo split, vectorized float4 -> 2x uint2
__global__ void convert_kernel(const float4* __restrict__ src,
                               uint2* __restrict__ hi, uint2* __restrict__ lo,
                               int n4) {
    for (int i = blockIdx.x * blockDim.x + threadIdx.x; i < n4;
         i += gridDim.x * blockDim.x) {
        float4 v = src[i];
        uint2 h, l;
        split2(v.x, v.y, h.x, l.x);
        split2(v.z, v.w, h.y, l.y);
        hi[i] = h;
        lo[i] = l;
    }
}

// one warp per token: logits, softmax-max prob, argmax, loss atomics
__global__ void router_kernel(const float* __restrict__ x,
                              const float* __restrict__ Wr,
                              const float* __restrict__ br) {
    int warp = (blockIdx.x * blockDim.x + threadIdx.x) >> 5;
    int lane = threadIdx.x & 31;
    if (warp >= T_TOK) return;

    const float4* x4 = reinterpret_cast<const float4*>(x) + (size_t)warp * (D_MODEL / 4);
    const float4* w4 = reinterpret_cast<const float4*>(Wr);

    float acc[N_EXP];
#pragma unroll
    for (int e = 0; e < N_EXP; e++) acc[e] = 0.f;

    for (int j = lane; j < D_MODEL / 4; j += 32) {
        float4 v = x4[j];
#pragma unroll
        for (int e = 0; e < N_EXP; e++) {
            float4 w = w4[e * (D_MODEL / 4) + j];
            acc[e] += v.x * w.x + v.y * w.y + v.z * w.z + v.w * w.w;
        }
    }
#pragma unroll
    for (int e = 0; e < N_EXP; e++) {
#pragma unroll
        for (int s = 16; s > 0; s >>= 1)
            acc[e] += __shfl_xor_sync(0xffffffff, acc[e], s);
    }
    if (lane == 0) {
        float lg[N_EXP];
        float mx = -1e30f;
        int mi = 0;
#pragma unroll
        for (int e = 0; e < N_EXP; e++) {
            lg[e] = acc[e] + br[e];
            if (lg[e] > mx) { mx = lg[e]; mi = e; }
        }
        float s = 0.f;
#pragma unroll
        for (int e = 0; e < N_EXP; e++) s += expf(lg[e] - mx);
        float topp = 1.f / s;
        g_idx[warp] = mi;
        g_topp[warp] = topp;
        atomicAdd(&g_cnt[mi], 1);
        atomicAdd(&g_tsum[mi], topp);
    }
}

__global__ void offsets_loss_kernel(float* __restrict__ out, int out_size) {
    if (threadIdx.x == 0) {
        int o = 0;
        double loss = 0.0;
        for (int e = 0; e < N_EXP; e++) {
            g_off[e] = o;
            o += g_cnt[e];
            double fr = (double)g_cnt[e] / (double)T_TOK;
            double pr = (double)g_tsum[e] / ((double)T_TOK * (double)T_TOK);
            loss += fr * pr;
        }
        loss *= (double)LOSS_SCALE * (double)N_EXP;
        long long ysz = (long long)T_TOK * D_MODEL;
        if ((long long)out_size > ysz) out[ysz] = (float)loss;
    }
}

__global__ void scatter_kernel() {
    int t = blockIdx.x * blockDim.x + threadIdx.x;
    if (t >= T_TOK) return;
    int e = g_idx[t];
    int pos = g_off[e] + atomicAdd(&g_cur[e], 1);
    g_list[pos] = t;
}

// ---------------- grouped GEMM (mma.sync bf16 3-term split) ------------------
// SMEM stage layout (65536 B per stage, 2 stages):
//   A_HI 0, A_LO 16384, B_HI 32768, B_LO 49152; each tile 128 rows x 128 B, SW128.
#define STG 65536
#define A_HI 0
#define A_LO 16384
#define B_HI 32768
#define B_LO 49152
#define SM_META 131072
#define GEMM_SMEM (SM_META + 1536)

__global__ __launch_bounds__(NTHREADS, 1)
void moe_gemm_kernel(const float* __restrict__ bias, float* __restrict__ out) {
    const int e = blockIdx.y;
    const int n_e = g_cnt[e];
    const int tile = blockIdx.x;
    if (tile * BM >= n_e) return;
    const int ntile = blockIdx.z;

    extern __shared__ char smem[];
    const uint32_t smem_base = smem_u32(smem);
    int* s_tok = (int*)(smem + SM_META);
    float* s_topp = (float*)(smem + SM_META + 512);
    float* s_bias = (float*)(smem + SM_META + 1024);

    const int tid = threadIdx.x;
    const int lane = tid & 31;
    const int wid = tid >> 5;
    const int wm = wid & 3;   // 4 m-groups of 32 rows
    const int wn = wid >> 2;  // 2 n-groups of 64 cols

    int n_rem = n_e - tile * BM;
    if (n_rem > BM) n_rem = BM;
    const int base_pos = g_off[e] + tile * BM;
    if (tid < BM) {
        int r = (tid < n_rem) ? tid : (n_rem - 1);
        int tk = g_list[base_pos + r];
        s_tok[tid] = tk;
        s_topp[tid] = g_topp[tk];
    }
    if (tid < BN) s_bias[tid] = bias[e * D_MODEL + ntile * BN + tid];
    __syncthreads();

    // ---- cp.async source/dst precompute: thread t copies rows (t>>3)+32j, 16B chunk (t&7)
    const int crow = tid >> 3;
    const int cc = tid & 7;
    const __nv_bfloat16* aHiSrc[4];
    const __nv_bfloat16* aLoSrc[4];
    const __nv_bfloat16* bHiSrc[4];
    const __nv_bfloat16* bLoSrc[4];
    uint32_t dstOff[4];
#pragma unroll
    for (int j = 0; j < 4; j++) {
        int row = crow + 32 * j;
        int tk = s_tok[row];
        aHiSrc[j] = g_Xhi + (size_t)tk * D_MODEL + cc * 8;
        aLoSrc[j] = g_Xlo + (size_t)tk * D_MODEL + cc * 8;
        size_t wrow = (size_t)e * D_MODEL + ntile * BN + row;
        bHiSrc[j] = g_Whi + wrow * D_MODEL + cc * 8;
        bLoSrc[j] = g_Wlo + wrow * D_MODEL + cc * 8;
        dstOff[j] = (uint32_t)(row * 128 + ((cc * 16) ^ ((row & 7) << 4)));
    }

    auto issue_copies = [&](int it) {
        uint32_t sb = smem_base + (uint32_t)(it & 1) * STG;
        size_t koff = (size_t)it * BK;
#pragma unroll
        for (int j = 0; j < 4; j++) {
            CP_ASYNC16(sb + A_HI + dstOff[j], aHiSrc[j] + koff);
            CP_ASYNC16(sb + A_LO + dstOff[j], aLoSrc[j] + koff);
            CP_ASYNC16(sb + B_HI + dstOff[j], bHiSrc[j] + koff);
            CP_ASYNC16(sb + B_LO + dstOff[j], bLoSrc[j] + koff);
        }
    };

    // ---- ldmatrix lane addressing (SW128: addr = row*128 + (kbyte ^ ((row&7)<<4)))
    const int rA = wm * 32 + ((lane >> 3) & 1) * 8 + (lane & 7);
    const uint32_t kA = ((lane >> 4) & 1) * 16;
    const uint32_t swA = (uint32_t)((rA & 7) << 4);
    const int rB0 = wn * 64 + ((lane >> 4) & 1) * 8 + (lane & 7);
    const uint32_t kB = ((lane >> 3) & 1) * 16;
    const uint32_t swB = (uint32_t)((lane & 7) << 4);

    float acc[2][8][4];
#pragma unroll
    for (int mt = 0; mt < 2; mt++)
#pragma unroll
        for (int nt = 0; nt < 8; nt++)
#pragma unroll
            for (int k = 0; k < 4; k++) acc[mt][nt][k] = 0.f;

    issue_copies(0);
    CP_COMMIT();

    for (int it = 0; it < KIT; it++) {
        if (it + 1 < KIT) {
            issue_copies(it + 1);
            CP_COMMIT();
            CP_WAIT1();
        } else {
            CP_WAIT0();
        }
        __syncthreads();

        const uint32_t stb = smem_base + (uint32_t)(it & 1) * STG;
#pragma unroll
        for (int ks = 0; ks < 4; ks++) {
            const uint32_t kxA = (uint32_t)(ks * 32 + kA) ^ swA;
            uint32_t ah[2][4], al[2][4];
#pragma unroll
            for (int mt = 0; mt < 2; mt++) {
                uint32_t ab = stb + (uint32_t)((rA + mt * 16) * 128) + kxA;
                ldsm4(ah[mt][0], ah[mt][1], ah[mt][2], ah[mt][3], ab + A_HI);
                ldsm4(al[mt][0], al[mt][1], al[mt][2], al[mt][3], ab + A_LO);
            }
            const uint32_t kxB = (uint32_t)(ks * 32 + kB) ^ swB;
#pragma unroll
            for (int p = 0; p < 4; p++) {
                uint32_t bb = stb + (uint32_t)((rB0 + p * 16) * 128) + kxB;
                uint32_t bh[4], bl[4];
                ldsm4(bh[0], bh[1], bh[2], bh[3], bb + B_HI);
                ldsm4(bl[0], bl[1], bl[2], bl[3], bb + B_LO);
#pragma unroll
                for (int mt = 0; mt < 2; mt++) {
                    mma16816(acc[mt][2 * p],     ah[mt], bh[0], bh[1]);
                    mma16816(acc[mt][2 * p],     ah[mt], bl[0], bl[1]);
                    mma16816(acc[mt][2 * p],     al[mt], bh[0], bh[1]);
                    mma16816(acc[mt][2 * p + 1], ah[mt], bh[2], bh[3]);
                    mma16816(acc[mt][2 * p + 1], ah[mt], bl[2], bl[3]);
                    mma16816(acc[mt][2 * p + 1], al[mt], bh[2], bh[3]);
                }
            }
        }
        __syncthreads();
    }

    // ---- epilogue: +bias, *topp, scatter by token ----
#pragma unroll
    for (int mt = 0; mt < 2; mt++) {
#pragma unroll
        for (int half = 0; half < 2; half++) {
            int row = wm * 32 + mt * 16 + (lane >> 2) + half * 8;
            if (row < n_rem) {
                int tk = s_tok[row];
                float tp = s_topp[row];
                float* op = out + (size_t)tk * D_MODEL + ntile * BN;
#pragma unroll
                for (int nt = 0; nt < 8; nt++) {
                    int col = wn * 64 + nt * 8 + (lane & 3) * 2;
                    float2 v;
                    v.x = (acc[mt][nt][half * 2 + 0] + s_bias[col]) * tp;
                    v.y = (acc[mt][nt][half * 2 + 1] + s_bias[col + 1]) * tp;
                    *(float2*)(op + col) = v;
                }
            }
        }
    }
}

// ---------------- launcher ---------------------------------------------------
extern "C" void kernel_launch(void* const* d_in, const int* in_sizes, int n_in,
                              void* d_out, int out_size) {
    const float* x  = (const float*)d_in[0];
    const float* Wr = (const float*)d_in[1];
    const float* br = (const float*)d_in[2];
    const float* W  = (const float*)d_in[3];
    const float* b  = (const float*)d_in[4];
    float* out = (float*)d_out;

    static int configured = 0;
    // cudaFuncSetAttribute is graph-capture-safe (host-side); call every time
    // to stay deterministic.
    cudaFuncSetAttribute(moe_gemm_kernel,
                         cudaFuncAttributeMaxDynamicSharedMemorySize, GEMM_SMEM);
    (void)configured;

    uint2 *whi, *wlo, *xhi, *xlo;
    cudaGetSymbolAddress((void**)&whi, g_Whi);
    cudaGetSymbolAddress((void**)&wlo, g_Wlo);
    cudaGetSymbolAddress((void**)&xhi, g_Xhi);
    cudaGetSymbolAddress((void**)&xlo, g_Xlo);

    init_kernel<<<1, 32>>>();
    convert_kernel<<<8192, 256>>>((const float4*)W, whi, wlo,
                                  N_EXP * D_MODEL * D_MODEL / 4);
    convert_kernel<<<4096, 256>>>((const float4*)x, xhi, xlo,
                                  T_TOK * D_MODEL / 4);
    router_kernel<<<T_TOK / 8, 256>>>(x, Wr, br);
    offsets_loss_kernel<<<1, 32>>>(out, out_size);
    scatter_kernel<<<T_TOK / 256, 256>>>();
    dim3 grid(T_TOK / BM, N_EXP, D_MODEL / BN);
    moe_gemm_kernel<<<grid, NTHREADS, GEMM_SMEM>>>(b, out);
}

// round 10
// speedup vs baseline: 1.9496x; 1.9496x over previous
#include <cuda_runtime.h>
#include <cuda_fp16.h>
#include <cstdint>
#include <cstddef>

#define D_MODEL 2048
#define N_EXP 8
#define T_TOK 8192
#define BM 128
#define BN 128
#define BK 64
#define KIT (D_MODEL / BK)
#define NTHREADS 256
#define LOSS_SCALE 3e-06f

// ---------------- device global scratch (no allocations allowed) ------------
__device__ int   g_cnt[N_EXP];
__device__ int   g_cur[N_EXP];
__device__ int   g_off[N_EXP];
__device__ float g_tsum[N_EXP];
__device__ int   g_idx[T_TOK];
__device__ float g_topp[T_TOK];
__device__ int   g_list[T_TOK];

// fp16 copies, precomputed once per launch
__device__ __half g_Wh[(size_t)N_EXP * D_MODEL * D_MODEL];
__device__ __half g_Xh[(size_t)T_TOK * D_MODEL];

// ---------------- helpers ----------------------------------------------------
__device__ __forceinline__ uint32_t smem_u32(const void* p) {
    uint32_t a;
    asm("{ .reg .u64 t; cvta.to.shared.u64 t, %1; cvt.u32.u64 %0, t; }"
        : "=r"(a) : "l"(p));
    return a;
}

#define CP_ASYNC16(dst, src) \
    asm volatile("cp.async.cg.shared.global [%0], [%1], 16;" \
        :: "r"(dst), "l"(src))
#define CP_COMMIT() asm volatile("cp.async.commit_group;")
#define CP_WAIT2()  asm volatile("cp.async.wait_group 2;")

__device__ __forceinline__ void ldsm4(uint32_t& r0, uint32_t& r1, uint32_t& r2,
                                      uint32_t& r3, uint32_t addr) {
    asm volatile("ldmatrix.sync.aligned.m8n8.x4.shared.b16 {%0,%1,%2,%3}, [%4];"
                 : "=r"(r0), "=r"(r1), "=r"(r2), "=r"(r3) : "r"(addr));
}

__device__ __forceinline__ void mma16816(float* c, const uint32_t* a,
                                         uint32_t b0, uint32_t b1) {
    asm volatile(
        "mma.sync.aligned.m16n8k16.row.col.f32.f16.f16.f32 "
        "{%0,%1,%2,%3}, {%4,%5,%6,%7}, {%8,%9}, {%0,%1,%2,%3};"
        : "+f"(c[0]), "+f"(c[1]), "+f"(c[2]), "+f"(c[3])
        : "r"(a[0]), "r"(a[1]), "r"(a[2]), "r"(a[3]), "r"(b0), "r"(b1));
}

// ---------------- small kernels ----------------------------------------------
__global__ void init_kernel() {
    int i = threadIdx.x;
    if (i < N_EXP) { g_cnt[i] = 0; g_cur[i] = 0; g_tsum[i] = 0.f; }
}

// fp32 -> fp16 convert, float4 -> uint2 (4 halves)
__global__ void convert_kernel(const float4* __restrict__ src,
                               uint2* __restrict__ dst, int n4) {
    for (int i = blockIdx.x * blockDim.x + threadIdx.x; i < n4;
         i += gridDim.x * blockDim.x) {
        float4 v = src[i];
        __half2 h0 = __floats2half2_rn(v.x, v.y);
        __half2 h1 = __floats2half2_rn(v.z, v.w);
        uint2 o;
        o.x = *(uint32_t*)&h0;
        o.y = *(uint32_t*)&h1;
        dst[i] = o;
    }
}

// one warp per 4 tokens: reuse Wr loads across tokens for issue density
__global__ void router_kernel(const float* __restrict__ x,
                              const float* __restrict__ Wr,
                              const float* __restrict__ br) {
    int warp = (blockIdx.x * blockDim.x + threadIdx.x) >> 5;
    int lane = threadIdx.x & 31;
    int t0 = warp * 4;
    if (t0 >= T_TOK) return;

    const float4* x4 = reinterpret_cast<const float4*>(x);
    const float4* w4 = reinterpret_cast<const float4*>(Wr);

    float acc[4][N_EXP];
#pragma unroll
    for (int t = 0; t < 4; t++)
#pragma unroll
        for (int e = 0; e < N_EXP; e++) acc[t][e] = 0.f;

    for (int j = lane; j < D_MODEL / 4; j += 32) {
        float4 w[N_EXP];
#pragma unroll
        for (int e = 0; e < N_EXP; e++) w[e] = w4[e * (D_MODEL / 4) + j];
#pragma unroll
        for (int t = 0; t < 4; t++) {
            float4 v = x4[(size_t)(t0 + t) * (D_MODEL / 4) + j];
#pragma unroll
            for (int e = 0; e < N_EXP; e++)
                acc[t][e] += v.x * w[e].x + v.y * w[e].y + v.z * w[e].z + v.w * w[e].w;
        }
    }
#pragma unroll
    for (int t = 0; t < 4; t++)
#pragma unroll
        for (int e = 0; e < N_EXP; e++) {
#pragma unroll
            for (int s = 16; s > 0; s >>= 1)
                acc[t][e] += __shfl_xor_sync(0xffffffff, acc[t][e], s);
        }
    if (lane == 0) {
#pragma unroll
        for (int t = 0; t < 4; t++) {
            float lg[N_EXP];
            float mx = -1e30f;
            int mi = 0;
#pragma unroll
            for (int e = 0; e < N_EXP; e++) {
                lg[e] = acc[t][e] + br[e];
                if (lg[e] > mx) { mx = lg[e]; mi = e; }
            }
            float s = 0.f;
#pragma unroll
            for (int e = 0; e < N_EXP; e++) s += expf(lg[e] - mx);
            float topp = 1.f / s;
            g_idx[t0 + t] = mi;
            g_topp[t0 + t] = topp;
            atomicAdd(&g_cnt[mi], 1);
            atomicAdd(&g_tsum[mi], topp);
        }
    }
}

__global__ void offsets_loss_kernel(float* __restrict__ out, int out_size) {
    if (threadIdx.x == 0) {
        int o = 0;
        double loss = 0.0;
        for (int e = 0; e < N_EXP; e++) {
            g_off[e] = o;
            o += g_cnt[e];
            double fr = (double)g_cnt[e] / (double)T_TOK;
            double pr = (double)g_tsum[e] / ((double)T_TOK * (double)T_TOK);
            loss += fr * pr;
        }
        loss *= (double)LOSS_SCALE * (double)N_EXP;
        long long ysz = (long long)T_TOK * D_MODEL;
        if ((long long)out_size > ysz) out[ysz] = (float)loss;
    }
}

__global__ void scatter_kernel() {
    int t = blockIdx.x * blockDim.x + threadIdx.x;
    if (t >= T_TOK) return;
    int e = g_idx[t];
    int pos = g_off[e] + atomicAdd(&g_cur[e], 1);
    g_list[pos] = t;
}

// ---------------- grouped GEMM (single fp16 mma.sync, 3-stage pipeline) ------
// Per stage: A 128x128B (16KB) + B 128x128B (16KB) = 32KB. 3 stages.
#define STG 32768
#define B_OFF 16384
#define NSTAGE 3
#define SM_META (NSTAGE * STG)
#define GEMM_SMEM (SM_META + 1536)

__global__ __launch_bounds__(NTHREADS)
void moe_gemm_kernel(const float* __restrict__ bias, float* __restrict__ out) {
    const int e = blockIdx.y;
    const int n_e = g_cnt[e];
    const int tile = blockIdx.x;
    if (tile * BM >= n_e) return;
    const int ntile = blockIdx.z;

    extern __shared__ char smem[];
    const uint32_t smem_base = smem_u32(smem);
    int* s_tok = (int*)(smem + SM_META);
    float* s_topp = (float*)(smem + SM_META + 512);
    float* s_bias = (float*)(smem + SM_META + 1024);

    const int tid = threadIdx.x;
    const int lane = tid & 31;
    const int wid = tid >> 5;
    const int wm = wid & 3;   // 4 m-groups of 32 rows
    const int wn = wid >> 2;  // 2 n-groups of 64 cols

    int n_rem = n_e - tile * BM;
    if (n_rem > BM) n_rem = BM;
    const int base_pos = g_off[e] + tile * BM;
    if (tid < BM) {
        int r = (tid < n_rem) ? tid : (n_rem - 1);
        int tk = g_list[base_pos + r];
        s_tok[tid] = tk;
        s_topp[tid] = g_topp[tk];
    }
    if (tid < BN) s_bias[tid] = bias[e * D_MODEL + ntile * BN + tid];
    __syncthreads();

    // cp.async mapping: thread t -> rows (t>>3)+32j, 16B chunk (t&7); SW128 dst
    const int crow = tid >> 3;
    const int cc = tid & 7;
    const __half* aSrc[4];
    const __half* bSrc[4];
    uint32_t dstOff[4];
#pragma unroll
    for (int j = 0; j < 4; j++) {
        int row = crow + 32 * j;
        int tk = s_tok[row];
        aSrc[j] = g_Xh + (size_t)tk * D_MODEL + cc * 8;
        size_t wrow = (size_t)e * D_MODEL + ntile * BN + row;
        bSrc[j] = g_Wh + wrow * D_MODEL + cc * 8;
        dstOff[j] = (uint32_t)(row * 128 + ((cc * 16) ^ ((row & 7) << 4)));
    }

    auto issue_copies = [&](int it) {
        uint32_t sb = smem_base + (uint32_t)(it % NSTAGE) * STG;
        size_t koff = (size_t)it * BK;
#pragma unroll
        for (int j = 0; j < 4; j++) {
            CP_ASYNC16(sb + dstOff[j], aSrc[j] + koff);
            CP_ASYNC16(sb + B_OFF + dstOff[j], bSrc[j] + koff);
        }
    };

    // ldmatrix lane addressing (SW128: addr = row*128 + (kbyte ^ ((row&7)<<4)))
    const int rA = wm * 32 + ((lane >> 3) & 1) * 8 + (lane & 7);
    const uint32_t kA = ((lane >> 4) & 1) * 16;
    const uint32_t swA = (uint32_t)((rA & 7) << 4);
    const int rB0 = wn * 64 + ((lane >> 4) & 1) * 8 + (lane & 7);
    const uint32_t kB = ((lane >> 3) & 1) * 16;
    const uint32_t swB = (uint32_t)((lane & 7) << 4);

    float acc[2][8][4];
#pragma unroll
    for (int mt = 0; mt < 2; mt++)
#pragma unroll
        for (int nt = 0; nt < 8; nt++)
#pragma unroll
            for (int k = 0; k < 4; k++) acc[mt][nt][k] = 0.f;

    issue_copies(0); CP_COMMIT();
    issue_copies(1); CP_COMMIT();
    issue_copies(2); CP_COMMIT();

    for (int it = 0; it < KIT; it++) {
        CP_WAIT2();           // stage (it) landed
        __syncthreads();

        const uint32_t stb = smem_base + (uint32_t)(it % NSTAGE) * STG;
#pragma unroll
        for (int ks = 0; ks < 4; ks++) {
            const uint32_t kxA = (uint32_t)(ks * 32 + kA) ^ swA;
            uint32_t ah[2][4];
#pragma unroll
            for (int mt = 0; mt < 2; mt++) {
                uint32_t ab = stb + (uint32_t)((rA + mt * 16) * 128) + kxA;
                ldsm4(ah[mt][0], ah[mt][1], ah[mt][2], ah[mt][3], ab);
            }
            const uint32_t kxB = (uint32_t)(ks * 32 + kB) ^ swB;
#pragma unroll
            for (int p = 0; p < 4; p++) {
                uint32_t bb = stb + B_OFF + (uint32_t)((rB0 + p * 16) * 128) + kxB;
                uint32_t bh[4];
                ldsm4(bh[0], bh[1], bh[2], bh[3], bb);
#pragma unroll
                for (int mt = 0; mt < 2; mt++) {
                    mma16816(acc[mt][2 * p],     ah[mt], bh[0], bh[1]);
                    mma16816(acc[mt][2 * p + 1], ah[mt], bh[2], bh[3]);
                }
            }
        }
        __syncthreads();      // all warps done reading stage (it)
        if (it + NSTAGE < KIT) issue_copies(it + NSTAGE);
        CP_COMMIT();          // always commit (possibly empty) to keep counts
    }

    // epilogue: +bias, *topp, scatter by token
#pragma unroll
    for (int mt = 0; mt < 2; mt++) {
#pragma unroll
        for (int half = 0; half < 2; half++) {
            int row = wm * 32 + mt * 16 + (lane >> 2) + half * 8;
            if (row < n_rem) {
                int tk = s_tok[row];
                float tp = s_topp[row];
                float* op = out + (size_t)tk * D_MODEL + ntile * BN;
#pragma unroll
                for (int nt = 0; nt < 8; nt++) {
                    int col = wn * 64 + nt * 8 + (lane & 3) * 2;
                    float2 v;
                    v.x = (acc[mt][nt][half * 2 + 0] + s_bias[col]) * tp;
                    v.y = (acc[mt][nt][half * 2 + 1] + s_bias[col + 1]) * tp;
                    *(float2*)(op + col) = v;
                }
            }
        }
    }
}

// ---------------- launcher ---------------------------------------------------
extern "C" void kernel_launch(void* const* d_in, const int* in_sizes, int n_in,
                              void* d_out, int out_size) {
    const float* x  = (const float*)d_in[0];
    const float* Wr = (const float*)d_in[1];
    const float* br = (const float*)d_in[2];
    const float* W  = (const float*)d_in[3];
    const float* b  = (const float*)d_in[4];
    float* out = (float*)d_out;

    cudaFuncSetAttribute(moe_gemm_kernel,
                         cudaFuncAttributeMaxDynamicSharedMemorySize, GEMM_SMEM);

    uint2 *wh, *xh;
    cudaGetSymbolAddress((void**)&wh, g_Wh);
    cudaGetSymbolAddress((void**)&xh, g_Xh);

    init_kernel<<<1, 32>>>();
    convert_kernel<<<8192, 256>>>((const float4*)W, wh,
                                  N_EXP * D_MODEL * D_MODEL / 4);
    convert_kernel<<<2048, 256>>>((const float4*)x, xh, T_TOK * D_MODEL / 4);
    router_kernel<<<T_TOK / 32, 256>>>(x, Wr, br);
    offsets_loss_kernel<<<1, 32>>>(out, out_size);
    scatter_kernel<<<T_TOK / 256, 256>>>();
    dim3 grid(T_TOK / BM, N_EXP, D_MODEL / BN);
    moe_gemm_kernel<<<grid, NTHREADS, GEMM_SMEM>>>(b, out);
}

// round 11
// speedup vs baseline: 2.4623x; 1.2630x over previous
#include <cuda_runtime.h>
#include <cuda_fp16.h>
#include <cstdint>
#include <cstddef>

#define D_MODEL 2048
#define N_EXP 8
#define T_TOK 8192
#define BM 128
#define BN 128
#define BK 64
#define KIT (D_MODEL / BK)
#define NTHREADS 256
#define LOSS_SCALE 3e-06f

// ---------------- device global scratch (no allocations allowed) ------------
__device__ int   g_cnt[N_EXP];
__device__ int   g_cur[N_EXP];
__device__ int   g_off[N_EXP];
__device__ float g_tsum[N_EXP];
__device__ int   g_idx[T_TOK];
__device__ float g_topp[T_TOK];
__device__ int   g_list[T_TOK];

// fp16 copies, precomputed once per launch
__device__ __half g_Wh[(size_t)N_EXP * D_MODEL * D_MODEL];
__device__ __half g_Xh[(size_t)T_TOK * D_MODEL];

// ---------------- helpers ----------------------------------------------------
__device__ __forceinline__ uint32_t smem_u32(const void* p) {
    uint32_t a;
    asm("{ .reg .u64 t; cvta.to.shared.u64 t, %1; cvt.u32.u64 %0, t; }"
        : "=r"(a) : "l"(p));
    return a;
}

#define CP_ASYNC16(dst, src) \
    asm volatile("cp.async.cg.shared.global [%0], [%1], 16;" \
        :: "r"(dst), "l"(src))
#define CP_COMMIT() asm volatile("cp.async.commit_group;")
#define CP_WAIT1()  asm volatile("cp.async.wait_group 1;")

__device__ __forceinline__ void ldsm4(uint32_t& r0, uint32_t& r1, uint32_t& r2,
                                      uint32_t& r3, uint32_t addr) {
    asm volatile("ldmatrix.sync.aligned.m8n8.x4.shared.b16 {%0,%1,%2,%3}, [%4];"
                 : "=r"(r0), "=r"(r1), "=r"(r2), "=r"(r3) : "r"(addr));
}

__device__ __forceinline__ void mma16816(float* c, const uint32_t* a,
                                         uint32_t b0, uint32_t b1) {
    asm volatile(
        "mma.sync.aligned.m16n8k16.row.col.f32.f16.f16.f32 "
        "{%0,%1,%2,%3}, {%4,%5,%6,%7}, {%8,%9}, {%0,%1,%2,%3};"
        : "+f"(c[0]), "+f"(c[1]), "+f"(c[2]), "+f"(c[3])
        : "r"(a[0]), "r"(a[1]), "r"(a[2]), "r"(a[3]), "r"(b0), "r"(b1));
}

// ---------------- small kernels ----------------------------------------------
__global__ void init_kernel() {
    int i = threadIdx.x;
    if (i < N_EXP) { g_cnt[i] = 0; g_cur[i] = 0; g_tsum[i] = 0.f; }
}

// fp32 -> fp16 convert (W only), float4 -> uint2 (4 halves)
__global__ void convert_kernel(const float4* __restrict__ src,
                               uint2* __restrict__ dst, int n4) {
    for (int i = blockIdx.x * blockDim.x + threadIdx.x; i < n4;
         i += gridDim.x * blockDim.x) {
        float4 v = src[i];
        __half2 h0 = __floats2half2_rn(v.x, v.y);
        __half2 h1 = __floats2half2_rn(v.z, v.w);
        uint2 o;
        o.x = *(uint32_t*)&h0;
        o.y = *(uint32_t*)&h1;
        dst[i] = o;
    }
}

// one warp per 4 tokens: router logits + fused x->fp16 conversion
__global__ void router_kernel(const float* __restrict__ x,
                              const float* __restrict__ Wr,
                              const float* __restrict__ br) {
    int warp = (blockIdx.x * blockDim.x + threadIdx.x) >> 5;
    int lane = threadIdx.x & 31;
    int t0 = warp * 4;
    if (t0 >= T_TOK) return;

    const float4* x4 = reinterpret_cast<const float4*>(x);
    const float4* w4 = reinterpret_cast<const float4*>(Wr);
    uint2* xh2 = reinterpret_cast<uint2*>(g_Xh);

    float acc[4][N_EXP];
#pragma unroll
    for (int t = 0; t < 4; t++)
#pragma unroll
        for (int e = 0; e < N_EXP; e++) acc[t][e] = 0.f;

    for (int j = lane; j < D_MODEL / 4; j += 32) {
        float4 w[N_EXP];
#pragma unroll
        for (int e = 0; e < N_EXP; e++) w[e] = w4[e * (D_MODEL / 4) + j];
#pragma unroll
        for (int t = 0; t < 4; t++) {
            float4 v = x4[(size_t)(t0 + t) * (D_MODEL / 4) + j];
            // fused fp16 conversion store
            __half2 h0 = __floats2half2_rn(v.x, v.y);
            __half2 h1 = __floats2half2_rn(v.z, v.w);
            uint2 o;
            o.x = *(uint32_t*)&h0;
            o.y = *(uint32_t*)&h1;
            xh2[(size_t)(t0 + t) * (D_MODEL / 4) + j] = o;
#pragma unroll
            for (int e = 0; e < N_EXP; e++)
                acc[t][e] += v.x * w[e].x + v.y * w[e].y + v.z * w[e].z + v.w * w[e].w;
        }
    }
#pragma unroll
    for (int t = 0; t < 4; t++)
#pragma unroll
        for (int e = 0; e < N_EXP; e++) {
#pragma unroll
            for (int s = 16; s > 0; s >>= 1)
                acc[t][e] += __shfl_xor_sync(0xffffffff, acc[t][e], s);
        }
    if (lane == 0) {
#pragma unroll
        for (int t = 0; t < 4; t++) {
            float lg[N_EXP];
            float mx = -1e30f;
            int mi = 0;
#pragma unroll
            for (int e = 0; e < N_EXP; e++) {
                lg[e] = acc[t][e] + br[e];
                if (lg[e] > mx) { mx = lg[e]; mi = e; }
            }
            float s = 0.f;
#pragma unroll
            for (int e = 0; e < N_EXP; e++) s += expf(lg[e] - mx);
            float topp = 1.f / s;
            g_idx[t0 + t] = mi;
            g_topp[t0 + t] = topp;
            atomicAdd(&g_cnt[mi], 1);
            atomicAdd(&g_tsum[mi], topp);
        }
    }
}

__global__ void offsets_loss_kernel(float* __restrict__ out, int out_size) {
    if (threadIdx.x == 0) {
        int o = 0;
        double loss = 0.0;
        for (int e = 0; e < N_EXP; e++) {
            g_off[e] = o;
            o += g_cnt[e];
            double fr = (double)g_cnt[e] / (double)T_TOK;
            double pr = (double)g_tsum[e] / ((double)T_TOK * (double)T_TOK);
            loss += fr * pr;
        }
        loss *= (double)LOSS_SCALE * (double)N_EXP;
        long long ysz = (long long)T_TOK * D_MODEL;
        if ((long long)out_size > ysz) out[ysz] = (float)loss;
    }
}

__global__ void scatter_kernel() {
    int t = blockIdx.x * blockDim.x + threadIdx.x;
    if (t >= T_TOK) return;
    int e = g_idx[t];
    int pos = g_off[e] + atomicAdd(&g_cur[e], 1);
    g_list[pos] = t;
}

// ---------------- grouped GEMM (fp16 mma.sync, 3-stage, single-sync loop) ----
// Per stage: A 128x128B (16KB) + B 128x128B (16KB) = 32KB. 3 stages.
#define STG 32768
#define B_OFF 16384
#define NSTAGE 3
#define SM_META (NSTAGE * STG)
#define GEMM_SMEM (SM_META + 1536)

__global__ __launch_bounds__(NTHREADS, 2)
void moe_gemm_kernel(const float* __restrict__ bias, float* __restrict__ out) {
    const int e = blockIdx.y;
    const int n_e = g_cnt[e];
    const int tile = blockIdx.x;
    if (tile * BM >= n_e) return;
    const int ntile = blockIdx.z;

    extern __shared__ char smem[];
    const uint32_t smem_base = smem_u32(smem);
    int* s_tok = (int*)(smem + SM_META);
    float* s_topp = (float*)(smem + SM_META + 512);
    float* s_bias = (float*)(smem + SM_META + 1024);

    const int tid = threadIdx.x;
    const int lane = tid & 31;
    const int wid = tid >> 5;
    const int wm = wid & 3;   // 4 m-groups of 32 rows
    const int wn = wid >> 2;  // 2 n-groups of 64 cols

    int n_rem = n_e - tile * BM;
    if (n_rem > BM) n_rem = BM;
    const int base_pos = g_off[e] + tile * BM;
    if (tid < BM) {
        int r = (tid < n_rem) ? tid : (n_rem - 1);
        int tk = g_list[base_pos + r];
        s_tok[tid] = tk;
        s_topp[tid] = g_topp[tk];
    }
    if (tid < BN) s_bias[tid] = bias[e * D_MODEL + ntile * BN + tid];
    __syncthreads();

    // cp.async mapping: thread t -> rows (t>>3)+32j, 16B chunk (t&7); SW128 dst
    const int crow = tid >> 3;
    const int cc = tid & 7;
    const __half* aSrc[4];
    const __half* bSrc[4];
    uint32_t dstOff[4];
#pragma unroll
    for (int j = 0; j < 4; j++) {
        int row = crow + 32 * j;
        int tk = s_tok[row];
        aSrc[j] = g_Xh + (size_t)tk * D_MODEL + cc * 8;
        size_t wrow = (size_t)e * D_MODEL + ntile * BN + row;
        bSrc[j] = g_Wh + wrow * D_MODEL + cc * 8;
        dstOff[j] = (uint32_t)(row * 128 + ((cc * 16) ^ ((row & 7) << 4)));
    }

    auto issue_copies = [&](int it) {
        uint32_t sb = smem_base + (uint32_t)(it % NSTAGE) * STG;
        size_t koff = (size_t)it * BK;
#pragma unroll
        for (int j = 0; j < 4; j++) {
            CP_ASYNC16(sb + dstOff[j], aSrc[j] + koff);
            CP_ASYNC16(sb + B_OFF + dstOff[j], bSrc[j] + koff);
        }
    };

    // ldmatrix lane addressing (SW128: addr = row*128 + (kbyte ^ ((row&7)<<4)))
    const int rA = wm * 32 + ((lane >> 3) & 1) * 8 + (lane & 7);
    const uint32_t kA = ((lane >> 4) & 1) * 16;
    const uint32_t swA = (uint32_t)((rA & 7) << 4);
    const int rB0 = wn * 64 + ((lane >> 4) & 1) * 8 + (lane & 7);
    const uint32_t kB = ((lane >> 3) & 1) * 16;
    const uint32_t swB = (uint32_t)((lane & 7) << 4);

    float acc[2][8][4];
#pragma unroll
    for (int mt = 0; mt < 2; mt++)
#pragma unroll
        for (int nt = 0; nt < 8; nt++)
#pragma unroll
            for (int k = 0; k < 4; k++) acc[mt][nt][k] = 0.f;

    // prologue: S-1 = 2 stages in flight
    issue_copies(0); CP_COMMIT();
    issue_copies(1); CP_COMMIT();

    for (int it = 0; it < KIT; it++) {
        CP_WAIT1();           // stage (it) landed (<=1 newer group pending)
        __syncthreads();      // also: all warps done reading slot (it-1)%3

        // refill the slot just vacated: stage it+2 -> slot (it-1)%3
        if (it + NSTAGE - 1 < KIT) issue_copies(it + NSTAGE - 1);
        CP_COMMIT();          // commit (possibly empty) to keep group counts

        const uint32_t stb = smem_base + (uint32_t)(it % NSTAGE) * STG;
#pragma unroll
        for (int ks = 0; ks < 4; ks++) {
            const uint32_t kxA = (uint32_t)(ks * 32 + kA) ^ swA;
            uint32_t ah[2][4];
#pragma unroll
            for (int mt = 0; mt < 2; mt++) {
                uint32_t ab = stb + (uint32_t)((rA + mt * 16) * 128) + kxA;
                ldsm4(ah[mt][0], ah[mt][1], ah[mt][2], ah[mt][3], ab);
            }
            const uint32_t kxB = (uint32_t)(ks * 32 + kB) ^ swB;
#pragma unroll
            for (int p = 0; p < 4; p++) {
                uint32_t bb = stb + B_OFF + (uint32_t)((rB0 + p * 16) * 128) + kxB;
                uint32_t bh[4];
                ldsm4(bh[0], bh[1], bh[2], bh[3], bb);
#pragma unroll
                for (int mt = 0; mt < 2; mt++) {
                    mma16816(acc[mt][2 * p],     ah[mt], bh[0], bh[1]);
                    mma16816(acc[mt][2 * p + 1], ah[mt], bh[2], bh[3]);
                }
            }
        }
    }

    // epilogue: +bias, *topp, scatter by token
#pragma unroll
    for (int mt = 0; mt < 2; mt++) {
#pragma unroll
        for (int half = 0; half < 2; half++) {
            int row = wm * 32 + mt * 16 + (lane >> 2) + half * 8;
            if (row < n_rem) {
                int tk = s_tok[row];
                float tp = s_topp[row];
                float* op = out + (size_t)tk * D_MODEL + ntile * BN;
#pragma unroll
                for (int nt = 0; nt < 8; nt++) {
                    int col = wn * 64 + nt * 8 + (lane & 3) * 2;
                    float2 v;
                    v.x = (acc[mt][nt][half * 2 + 0] + s_bias[col]) * tp;
                    v.y = (acc[mt][nt][half * 2 + 1] + s_bias[col + 1]) * tp;
                    *(float2*)(op + col) = v;
                }
            }
        }
    }
}

// ---------------- launcher ---------------------------------------------------
extern "C" void kernel_launch(void* const* d_in, const int* in_sizes, int n_in,
                              void* d_out, int out_size) {
    const float* x  = (const float*)d_in[0];
    const float* Wr = (const float*)d_in[1];
    const float* br = (const float*)d_in[2];
    const float* W  = (const float*)d_in[3];
    const float* b  = (const float*)d_in[4];
    float* out = (float*)d_out;

    cudaFuncSetAttribute(moe_gemm_kernel,
                         cudaFuncAttributeMaxDynamicSharedMemorySize, GEMM_SMEM);

    uint2* wh;
    cudaGetSymbolAddress((void**)&wh, g_Wh);

    init_kernel<<<1, 32>>>();
    convert_kernel<<<8192, 256>>>((const float4*)W, wh,
                                  N_EXP * D_MODEL * D_MODEL / 4);
    router_kernel<<<T_TOK / 32, 256>>>(x, Wr, br);
    offsets_loss_kernel<<<1, 32>>>(out, out_size);
    scatter_kernel<<<T_TOK / 256, 256>>>();
    dim3 grid(T_TOK / BM, N_EXP, D_MODEL / BN);
    moe_gemm_kernel<<<grid, NTHREADS, GEMM_SMEM>>>(b, out);
}